// round 2
// baseline (speedup 1.0000x reference)
#include <cuda_runtime.h>

// Problem constants
#define N_IMG 8
#define CIN   64
#define COUT  64
#define HH    128
#define WW    128
#define HW    16384            // 128*128
#define KTAPS 9
#define WELEMS (COUT*CIN*KTAPS)   // 36864

// Scratch (device globals: no allocation allowed in kernel_launch)
__device__ float g_xt[(size_t)N_IMG * HW * CIN];   // x transposed to NHWC
__device__ float g_wt[KTAPS * CIN * COUT];         // quantized weight, [ (k*64+c) ][ o ]

// ---------------------------------------------------------------------------
// Kernel 1: per-tensor symmetric weight quantization (8-bit) + transpose.
// Single block; reduce max|w|, then quantize & scatter to [k][c][o] layout.
// ---------------------------------------------------------------------------
__global__ void prep_weights_kernel(const float* __restrict__ w) {
    __shared__ float smax[32];
    int tid = threadIdx.x;

    float m = 0.f;
    for (int i = tid; i < WELEMS; i += blockDim.x)
        m = fmaxf(m, fabsf(w[i]));
    #pragma unroll
    for (int s = 16; s > 0; s >>= 1)
        m = fmaxf(m, __shfl_xor_sync(0xffffffffu, m, s));
    if ((tid & 31) == 0) smax[tid >> 5] = m;
    __syncthreads();
    if (tid < 32) {
        float v = (tid < (int)(blockDim.x >> 5)) ? smax[tid] : 0.f;
        #pragma unroll
        for (int s = 16; s > 0; s >>= 1)
            v = fmaxf(v, __shfl_xor_sync(0xffffffffu, v, s));
        if (tid == 0) smax[0] = v;
    }
    __syncthreads();

    const float scale = fmaxf(smax[0], 1e-8f) / 127.0f;

    for (int i = tid; i < WELEMS; i += blockDim.x) {
        // IEEE-exact div / rint / mul to match jnp regardless of --use_fast_math
        float q = rintf(__fdiv_rn(w[i], scale));
        q = fminf(fmaxf(q, -128.0f), 127.0f);
        float wq = __fmul_rn(q, scale);
        int o   = i / (CIN * KTAPS);
        int rem = i - o * (CIN * KTAPS);
        int c   = rem / KTAPS;
        int k   = rem - c * KTAPS;
        g_wt[(k * CIN + c) * COUT + o] = wq;
    }
}

// ---------------------------------------------------------------------------
// Kernel 2: transpose x from NCHW to NHWC (so a bilinear corner gather reads
// 64 contiguous floats = 2 cache lines instead of 64 strided lines).
// ---------------------------------------------------------------------------
__global__ void transpose_kernel(const float* __restrict__ x) {
    __shared__ float tile[32][33];
    int n  = blockIdx.z;
    int c0 = blockIdx.y << 5;
    int p0 = blockIdx.x << 5;
    int tx = threadIdx.x;   // 0..31
    int ty = threadIdx.y;   // 0..7

    const float* xp = x + ((size_t)(n * CIN + c0)) * HW + p0;
    #pragma unroll
    for (int i = 0; i < 4; ++i)
        tile[ty + i * 8][tx] = xp[(size_t)(ty + i * 8) * HW + tx];
    __syncthreads();

    float* op = g_xt + ((size_t)n * HW + p0) * CIN + c0;
    #pragma unroll
    for (int i = 0; i < 4; ++i)
        op[(size_t)(ty + i * 8) * CIN + tx] = tile[tx][ty + i * 8];
}

// ---------------------------------------------------------------------------
// Kernel 3: fused bilinear sampling + implicit GEMM.
// Block: 128 threads, tile = 128 pixels x 64 outputs, K = 576 processed
// tap-by-tap (9 x 64 channels). Thread tile 8x8 registers.
//   As[c][px]  (64 x 128 fp32, 32KB)  -- sampled activations (transposed)
//   Bs[c][o]   (64 x  64 fp32, 16KB)  -- quantized weights for this tap
// ---------------------------------------------------------------------------
__global__ __launch_bounds__(128, 4) void deform_gemm_kernel(
    const float* __restrict__ offset, float* __restrict__ out)
{
    __shared__ float As[CIN][128];
    __shared__ float Bs[CIN][COUT];

    const int t   = threadIdx.x;          // 0..127 ; owns pixel t in the tile
    const int pb  = blockIdx.x << 7;      // global pixel base (tile of 128)
    const int n   = pb >> 14;             // image index (HW = 16384 = 2^14)
    const int lpb = pb & (HW - 1);        // pixel base within image
    const int lp  = lpb + t;
    const int ho  = lp >> 7;
    const int wo  = lp & 127;

    const float* xb   = g_xt + ((size_t)n << 20);           // n * HW * CIN
    const float* offb = offset + (size_t)n * 18 * HW + lp;

    const int ty = t >> 3;   // 0..15  pixel group
    const int tx = t & 7;    // 0..7   output group

    // Prefetch all 18 offset values for this pixel up front (independent
    // LDGs issue back-to-back; removes 2 dependent loads from each tap's
    // critical path before the As fill).
    float offv[2 * KTAPS];
    #pragma unroll
    for (int k = 0; k < 2 * KTAPS; ++k)
        offv[k] = __ldg(offb + k * HW);

    float acc[8][8];
    #pragma unroll
    for (int r = 0; r < 8; ++r)
        #pragma unroll
        for (int j = 0; j < 8; ++j)
            acc[r][j] = 0.f;

    #pragma unroll 1
    for (int k = 0; k < KTAPS; ++k) {
        // ---- load B tile (this tap's weights, already [c][o]) ----
        {
            const float4* wt4 = reinterpret_cast<const float4*>(g_wt + k * CIN * COUT);
            float4* bs4 = reinterpret_cast<float4*>(&Bs[0][0]);
            #pragma unroll
            for (int i = 0; i < 8; ++i)
                bs4[t + i * 128] = wt4[t + i * 128];
        }

        // ---- bilinear sample this tap for pixel t, all 64 channels ----
        {
            const int ky = k / 3;
            const int kx = k - ky * 3;
            const float py = (float)(ho - 1 + ky) + offv[2 * k];
            const float px = (float)(wo - 1 + kx) + offv[2 * k + 1];
            const float fy0 = floorf(py), fx0 = floorf(px);
            const float dy = py - fy0, dx = px - fx0;
            const int iy0 = (int)fy0, ix0 = (int)fx0;
            const int iy1 = iy0 + 1,  ix1 = ix0 + 1;

            float w00 = (1.f - dy) * (1.f - dx);
            float w01 = (1.f - dy) * dx;
            float w10 = dy * (1.f - dx);
            float w11 = dy * dx;

            const bool vy0 = ((unsigned)iy0 < 128u);
            const bool vy1 = ((unsigned)iy1 < 128u);
            const bool vx0 = ((unsigned)ix0 < 128u);
            const bool vx1 = ((unsigned)ix1 < 128u);
            if (!(vy0 && vx0)) w00 = 0.f;
            if (!(vy0 && vx1)) w01 = 0.f;
            if (!(vy1 && vx0)) w10 = 0.f;
            if (!(vy1 && vx1)) w11 = 0.f;

            const int cy0 = min(max(iy0, 0), 127);
            const int cy1 = min(max(iy1, 0), 127);
            const int cx0 = min(max(ix0, 0), 127);
            const int cx1 = min(max(ix1, 0), 127);

            const float4* p00 = reinterpret_cast<const float4*>(xb + (size_t)((cy0 << 7) + cx0) * CIN);
            const float4* p01 = reinterpret_cast<const float4*>(xb + (size_t)((cy0 << 7) + cx1) * CIN);
            const float4* p10 = reinterpret_cast<const float4*>(xb + (size_t)((cy1 << 7) + cx0) * CIN);
            const float4* p11 = reinterpret_cast<const float4*>(xb + (size_t)((cy1 << 7) + cx1) * CIN);

            #pragma unroll 4
            for (int cg = 0; cg < 16; ++cg) {
                const float4 v00 = __ldg(p00 + cg);
                const float4 v01 = __ldg(p01 + cg);
                const float4 v10 = __ldg(p10 + cg);
                const float4 v11 = __ldg(p11 + cg);
                float sx = w00 * v00.x + w01 * v01.x + w10 * v10.x + w11 * v11.x;
                float sy = w00 * v00.y + w01 * v01.y + w10 * v10.y + w11 * v11.y;
                float sz = w00 * v00.z + w01 * v01.z + w10 * v10.z + w11 * v11.z;
                float sw = w00 * v00.w + w01 * v01.w + w10 * v10.w + w11 * v11.w;
                As[cg * 4 + 0][t] = sx;
                As[cg * 4 + 1][t] = sy;
                As[cg * 4 + 2][t] = sz;
                As[cg * 4 + 3][t] = sw;
            }
        }
        __syncthreads();

        // ---- GEMM accumulate over this tap's 64 channels ----
        {
            const float4* as4 = reinterpret_cast<const float4*>(&As[0][0]);
            const float4* bs4 = reinterpret_cast<const float4*>(&Bs[0][0]);
            #pragma unroll 4
            for (int c = 0; c < CIN; ++c) {
                const float4 a0 = as4[c * 32 + ty * 2];
                const float4 a1 = as4[c * 32 + ty * 2 + 1];
                const float4 b0 = bs4[c * 16 + tx * 2];
                const float4 b1 = bs4[c * 16 + tx * 2 + 1];
                const float a[8] = {a0.x, a0.y, a0.z, a0.w, a1.x, a1.y, a1.z, a1.w};
                const float b[8] = {b0.x, b0.y, b0.z, b0.w, b1.x, b1.y, b1.z, b1.w};
                #pragma unroll
                for (int r = 0; r < 8; ++r)
                    #pragma unroll
                    for (int j = 0; j < 8; ++j)
                        acc[r][j] += a[r] * b[j];
            }
        }
        __syncthreads();
    }

    // ---- write out [n][o][lp] ----
    float* ob = out + (size_t)(n * COUT) * HW + lpb;
    #pragma unroll
    for (int j = 0; j < 8; ++j) {
        const int o = tx * 8 + j;
        float* orow = ob + (size_t)o * HW + ty * 8;
        float4 v0 = make_float4(acc[0][j], acc[1][j], acc[2][j], acc[3][j]);
        float4 v1 = make_float4(acc[4][j], acc[5][j], acc[6][j], acc[7][j]);
        reinterpret_cast<float4*>(orow)[0] = v0;
        reinterpret_cast<float4*>(orow)[1] = v1;
    }
}

// ---------------------------------------------------------------------------
extern "C" void kernel_launch(void* const* d_in, const int* in_sizes, int n_in,
                              void* d_out, int out_size)
{
    const float* x      = (const float*)d_in[0];   // [8,64,128,128]
    const float* offset = (const float*)d_in[1];   // [8,18,128,128]
    const float* weight = (const float*)d_in[2];   // [64,64,3,3]
    float* out = (float*)d_out;                    // [8,64,128,128]

    prep_weights_kernel<<<1, 1024>>>(weight);
    transpose_kernel<<<dim3(HW / 32, CIN / 32, N_IMG), dim3(32, 8)>>>(x);
    deform_gemm_kernel<<<(N_IMG * HW) / 128, 128>>>(offset, out);
}

// round 6
// speedup vs baseline: 1.3015x; 1.3015x over previous
#include <cuda_runtime.h>

// Problem constants
#define N_IMG 8
#define CIN   64
#define COUT  64
#define HH    128
#define WW    128
#define HW    16384            // 128*128
#define KTAPS 9
#define WELEMS (COUT*CIN*KTAPS)   // 36864

// Scratch (device globals: no allocation allowed in kernel_launch)
__device__ float g_xt[(size_t)N_IMG * HW * CIN];   // x transposed to NHWC
__device__ float g_wt[KTAPS * CIN * COUT];         // quantized weight, [ (k*64+c) ][ o ]
__device__ int   g_max_bits;                       // max|w| as int bits (nonneg float)

// ---------------------------------------------------------------------------
// Weight prep, parallelized: reset -> grid max-reduce -> grid quantize+scatter
// ---------------------------------------------------------------------------
__global__ void reset_max_kernel() { g_max_bits = 0; }

__global__ void max_reduce_kernel(const float* __restrict__ w) {
    __shared__ float smax[32];
    int i = blockIdx.x * 1024 + threadIdx.x;
    float m = (i < WELEMS) ? fabsf(w[i]) : 0.f;
    #pragma unroll
    for (int s = 16; s > 0; s >>= 1)
        m = fmaxf(m, __shfl_xor_sync(0xffffffffu, m, s));
    if ((threadIdx.x & 31) == 0) smax[threadIdx.x >> 5] = m;
    __syncthreads();
    if (threadIdx.x < 32) {
        float v = smax[threadIdx.x];
        #pragma unroll
        for (int s = 16; s > 0; s >>= 1)
            v = fmaxf(v, __shfl_xor_sync(0xffffffffu, v, s));
        if (threadIdx.x == 0)
            atomicMax(&g_max_bits, __float_as_int(v));  // nonneg: int order == float order
    }
}

__global__ void quantize_kernel(const float* __restrict__ w) {
    const float scale = fmaxf(__int_as_float(g_max_bits), 1e-8f) / 127.0f;
    int i = blockIdx.x * 256 + threadIdx.x;
    if (i >= WELEMS) return;
    // IEEE-exact div / rint / mul to match jnp regardless of --use_fast_math
    float q = rintf(__fdiv_rn(w[i], scale));
    q = fminf(fmaxf(q, -128.0f), 127.0f);
    float wq = __fmul_rn(q, scale);
    int o   = i / (CIN * KTAPS);
    int rem = i - o * (CIN * KTAPS);
    int c   = rem / KTAPS;
    int k   = rem - c * KTAPS;
    g_wt[(k * CIN + c) * COUT + o] = wq;
}

// ---------------------------------------------------------------------------
// Kernel 2: transpose x from NCHW to NHWC (bilinear corner gather becomes
// 2 contiguous cache lines per corner instead of 64 strided lines).
// ---------------------------------------------------------------------------
__global__ void transpose_kernel(const float* __restrict__ x) {
    __shared__ float tile[32][33];
    int n  = blockIdx.z;
    int c0 = blockIdx.y << 5;
    int p0 = blockIdx.x << 5;
    int tx = threadIdx.x;   // 0..31
    int ty = threadIdx.y;   // 0..7

    const float* xp = x + ((size_t)(n * CIN + c0)) * HW + p0;
    #pragma unroll
    for (int i = 0; i < 4; ++i)
        tile[ty + i * 8][tx] = xp[(size_t)(ty + i * 8) * HW + tx];
    __syncthreads();

    float* op = g_xt + ((size_t)n * HW + p0) * CIN + c0;
    #pragma unroll
    for (int i = 0; i < 4; ++i)
        op[(size_t)(ty + i * 8) * CIN + tx] = tile[tx][ty + i * 8];
}

// ---------------------------------------------------------------------------
// Kernel 3: fused bilinear sampling + implicit GEMM.
// 128 threads, tile = 128 pixels x 64 outputs, 9 taps x 64 channels.
//
// Sampling is COALESCED: each thread computes its own pixel's 4 corner
// indices + weights; then 16-lane groups cooperatively gather one pixel's
// 64 channels (4 corners x contiguous 256B) via __shfl broadcast of the
// corner data. 4 L1 wavefronts per warp-LDG instead of 32.
//
//   As[px][64]  (32KB)  sampled activations
//   Bs[c][64]   (16KB)  this tap's quantized weights
// ---------------------------------------------------------------------------
__global__ __launch_bounds__(128, 4) void deform_gemm_kernel(
    const float* __restrict__ offset, float* __restrict__ out)
{
    __shared__ float As[128 * 64];
    __shared__ float Bs[CIN * COUT];

    const int t   = threadIdx.x;          // 0..127 ; owns pixel t for addressing
    const int pb  = blockIdx.x << 7;      // global pixel base (tile of 128)
    const int n   = pb >> 14;             // image index (HW = 16384 = 2^14)
    const int lpb = pb & (HW - 1);        // pixel base within image
    const int lp  = lpb + t;
    const int ho  = lp >> 7;
    const int wo  = lp & 127;

    const float4* xb4  = reinterpret_cast<const float4*>(g_xt + ((size_t)n << 20));
    const float*  offb = offset + (size_t)n * 18 * HW + lp;

    const int ty = t >> 3;    // 0..15  pixel group (GEMM)
    const int tx = t & 7;     // 0..7   output group (GEMM)
    const int lane = t & 31;
    const int wrp  = t >> 5;  // warp id: handles pixels [32*wrp, 32*wrp+32)
    const int g    = lane & 15;      // channel-chunk lane within 16-group
    const int sel  = lane >> 4;      // which of the 2 concurrent pixels

    float acc[8][8];
    #pragma unroll
    for (int r = 0; r < 8; ++r)
        #pragma unroll
        for (int j = 0; j < 8; ++j)
            acc[r][j] = 0.f;

    #pragma unroll 1
    for (int k = 0; k < KTAPS; ++k) {
        // ---- load B tile (this tap's weights, already [c][o]) ----
        {
            const float4* wt4 = reinterpret_cast<const float4*>(g_wt + k * CIN * COUT);
            float4* bs4 = reinterpret_cast<float4*>(Bs);
            #pragma unroll
            for (int i = 0; i < 8; ++i)
                bs4[t + i * 128] = wt4[t + i * 128];
        }

        // ---- per-thread corner math for its own pixel ----
        int   i00, i01, i10, i11;     // pixel index of each corner (row*128+col)
        float w00, w01, w10, w11;
        {
            const int ky = k / 3;
            const int kx = k - ky * 3;
            const float offy = __ldg(offb + (2 * k) * HW);
            const float offx = __ldg(offb + (2 * k + 1) * HW);
            const float py = (float)(ho - 1 + ky) + offy;
            const float px = (float)(wo - 1 + kx) + offx;
            const float fy0 = floorf(py), fx0 = floorf(px);
            const float dy = py - fy0, dx = px - fx0;
            const int iy0 = (int)fy0, ix0 = (int)fx0;
            const int iy1 = iy0 + 1,  ix1 = ix0 + 1;

            w00 = (1.f - dy) * (1.f - dx);
            w01 = (1.f - dy) * dx;
            w10 = dy * (1.f - dx);
            w11 = dy * dx;

            const bool vy0 = ((unsigned)iy0 < 128u);
            const bool vy1 = ((unsigned)iy1 < 128u);
            const bool vx0 = ((unsigned)ix0 < 128u);
            const bool vx1 = ((unsigned)ix1 < 128u);
            if (!(vy0 && vx0)) w00 = 0.f;
            if (!(vy0 && vx1)) w01 = 0.f;
            if (!(vy1 && vx0)) w10 = 0.f;
            if (!(vy1 && vx1)) w11 = 0.f;

            const int cy0 = min(max(iy0, 0), 127);
            const int cy1 = min(max(iy1, 0), 127);
            const int cx0 = min(max(ix0, 0), 127);
            const int cx1 = min(max(ix1, 0), 127);

            i00 = (cy0 << 7) + cx0;
            i01 = (cy0 << 7) + cx1;
            i10 = (cy1 << 7) + cx0;
            i11 = (cy1 << 7) + cx1;
        }

        // ---- cooperative coalesced gather: 16 lanes per pixel ----
        // Warp w handles its own pixels 32w..32w+31, two per iteration.
        #pragma unroll 2
        for (int it = 0; it < 16; ++it) {
            const int src = 2 * it + sel;          // lane holding this pixel's data
            const int b00 = __shfl_sync(0xffffffffu, i00, src);
            const int b01 = __shfl_sync(0xffffffffu, i01, src);
            const int b10 = __shfl_sync(0xffffffffu, i10, src);
            const int b11 = __shfl_sync(0xffffffffu, i11, src);
            const float c00 = __shfl_sync(0xffffffffu, w00, src);
            const float c01 = __shfl_sync(0xffffffffu, w01, src);
            const float c10 = __shfl_sync(0xffffffffu, w10, src);
            const float c11 = __shfl_sync(0xffffffffu, w11, src);

            const float4 v00 = __ldg(xb4 + b00 * 16 + g);
            const float4 v01 = __ldg(xb4 + b01 * 16 + g);
            const float4 v10 = __ldg(xb4 + b10 * 16 + g);
            const float4 v11 = __ldg(xb4 + b11 * 16 + g);

            float4 s;
            s.x = c00 * v00.x + c01 * v01.x + c10 * v10.x + c11 * v11.x;
            s.y = c00 * v00.y + c01 * v01.y + c10 * v10.y + c11 * v11.y;
            s.z = c00 * v00.z + c01 * v01.z + c10 * v10.z + c11 * v11.z;
            s.w = c00 * v00.w + c01 * v01.w + c10 * v10.w + c11 * v11.w;

            const int pxl = (wrp << 5) + 2 * it + sel;   // local pixel 0..127
            reinterpret_cast<float4*>(As + pxl * 64)[g] = s;
        }
        __syncthreads();

        // ---- GEMM accumulate over this tap's 64 channels ----
        {
            const float* arow = As + (ty * 8) * 64;
            #pragma unroll 2
            for (int c = 0; c < CIN; ++c) {
                float a[8];
                #pragma unroll
                for (int r = 0; r < 8; ++r)
                    a[r] = arow[r * 64 + c];
                const float4 b0 = reinterpret_cast<const float4*>(Bs + c * 64 + tx * 8)[0];
                const float4 b1 = reinterpret_cast<const float4*>(Bs + c * 64 + tx * 8)[1];
                const float b[8] = {b0.x, b0.y, b0.z, b0.w, b1.x, b1.y, b1.z, b1.w};
                #pragma unroll
                for (int r = 0; r < 8; ++r)
                    #pragma unroll
                    for (int j = 0; j < 8; ++j)
                        acc[r][j] += a[r] * b[j];
            }
        }
        __syncthreads();
    }

    // ---- write out [n][o][lp] ----
    float* ob = out + (size_t)(n * COUT) * HW + lpb;
    #pragma unroll
    for (int j = 0; j < 8; ++j) {
        const int o = tx * 8 + j;
        float* orow = ob + (size_t)o * HW + ty * 8;
        float4 v0 = make_float4(acc[0][j], acc[1][j], acc[2][j], acc[3][j]);
        float4 v1 = make_float4(acc[4][j], acc[5][j], acc[6][j], acc[7][j]);
        reinterpret_cast<float4*>(orow)[0] = v0;
        reinterpret_cast<float4*>(orow)[1] = v1;
    }
}

// ---------------------------------------------------------------------------
extern "C" void kernel_launch(void* const* d_in, const int* in_sizes, int n_in,
                              void* d_out, int out_size)
{
    const float* x      = (const float*)d_in[0];   // [8,64,128,128]
    const float* offset = (const float*)d_in[1];   // [8,18,128,128]
    const float* weight = (const float*)d_in[2];   // [64,64,3,3]
    float* out = (float*)d_out;                    // [8,64,128,128]

    reset_max_kernel<<<1, 1>>>();
    max_reduce_kernel<<<WELEMS / 1024, 1024>>>(weight);
    quantize_kernel<<<WELEMS / 256, 256>>>(weight);
    transpose_kernel<<<dim3(HW / 32, CIN / 32, N_IMG), dim3(32, 8)>>>(x);
    deform_gemm_kernel<<<(N_IMG * HW) / 128, 128>>>(offset, out);
}